// round 12
// baseline (speedup 1.0000x reference)
#include <cuda_runtime.h>

// Problem constants (fixed by the reference)
#define BSZ    2
#define LEN    2048
#define DQ     512
#define SQ     4
#define SH     2                 // s-lanes per thread (K1 and K3)
#define NC     128               // fine chunks along L (all kernels)
#define CHUNKF (LEN / NC)        // 16 steps per fine chunk
#define NCL    (NC / 32)         // fine chunks per lane in K2 warp scan (4)
#define EPSQ   1e-6f

typedef unsigned long long u64;

// Scratch: chunk summaries and carries, laid out [b][chunk][s][d] as float4.
__device__ float4 g_Q  [BSZ * NC * SQ * DQ];
__device__ float4 g_H  [BSZ * NC * SQ * DQ];
__device__ float4 g_Hin[BSZ * NC * SQ * DQ];

// ---------------------------------------------------------------------------
// f32x2 primitives. Values are packed over the thread's s-pair: (s0, s1).
// Only add/mul/fma f32x2 are used (no sub/neg needed).
// ---------------------------------------------------------------------------
__device__ __forceinline__ u64 pk(float lo, float hi) {
    u64 r; asm("mov.b64 %0, {%1, %2};" : "=l"(r) : "f"(lo), "f"(hi)); return r;
}
__device__ __forceinline__ void upk(float& lo, float& hi, u64 v) {
    asm("mov.b64 {%0, %1}, %2;" : "=f"(lo), "=f"(hi) : "l"(v));
}
__device__ __forceinline__ u64 fma2(u64 a, u64 b, u64 c) {
    u64 r; asm("fma.rn.f32x2 %0, %1, %2, %3;" : "=l"(r) : "l"(a), "l"(b), "l"(c)); return r;
}
__device__ __forceinline__ u64 add2(u64 a, u64 b) {
    u64 r; asm("add.rn.f32x2 %0, %1, %2;" : "=l"(r) : "l"(a), "l"(b)); return r;
}
__device__ __forceinline__ u64 mul2(u64 a, u64 b) {
    u64 r; asm("mul.rn.f32x2 %0, %1, %2;" : "=l"(r) : "l"(a), "l"(b)); return r;
}
__device__ __forceinline__ u64 neg2(u64 a) { return a ^ 0x8000000080000000ULL; }

#define ONE2  0x3F8000003F800000ULL   // (1.0f, 1.0f)
#define NONE2 0xBF800000BF800000ULL   // (-1.0f, -1.0f)
#define EPS2  0x358637BD358637BDULL   // (1e-6f, 1e-6f)

// Packed quaternion: each component is an f32x2 over the s-pair.
struct P4 { u64 x, y, z, w; };
// Packed quaternion with precomputed negated y/z/w (for left operand of mul).
struct Q2 { u64 x, y, z, w, ny, nz, nw; };

__device__ __forceinline__ Q2 mkq2(u64 x, u64 y, u64 z, u64 w) {
    Q2 q; q.x = x; q.y = y; q.z = z; q.w = w;
    q.ny = neg2(y); q.nz = neg2(z); q.nw = neg2(w);
    return q;
}

// r = a (x) b + c, all packed over s-pair (16 FFMA2, signs via a.n*)
__device__ __forceinline__ P4 qmad2(const Q2& a, const P4& b, const P4& c) {
    P4 r;
    r.x = fma2(a.x, b.x, fma2(a.ny, b.y, fma2(a.nz, b.z, fma2(a.nw, b.w, c.x))));
    r.y = fma2(a.x, b.y, fma2(a.y,  b.x, fma2(a.z,  b.w, fma2(a.nw, b.z, c.y))));
    r.z = fma2(a.x, b.z, fma2(a.ny, b.w, fma2(a.z,  b.x, fma2(a.w,  b.y, c.z))));
    r.w = fma2(a.x, b.w, fma2(a.y,  b.z, fma2(a.nz, b.y, fma2(a.w,  b.x, c.w))));
    return r;
}

__device__ __forceinline__ float frcp(float x) {
    float r; asm("rcp.approx.f32 %0, %1;" : "=f"(r) : "f"(x)); return r;
}

// Packed transition quaternion for the s-pair.
// ah2 = packed 0.5*A components; nahx2 = neg2(ah2.x) precomputed.
__device__ __forceinline__ Q2 step_q2(u64 dt2, const P4& ah2, u64 nahx2) {
    const u64 wx = mul2(dt2, ah2.x);
    const u64 wy = mul2(dt2, ah2.y);
    const u64 wz = mul2(dt2, ah2.z);
    const u64 ww = mul2(dt2, ah2.w);
    const u64 omr = fma2(dt2, nahx2, ONE2);               // 1 - wr
    const u64 vve = fma2(wy, wy, fma2(wz, wz, fma2(ww, ww, EPS2)));
    const u64 n2  = fma2(omr, omr, vve);
    float na, nb; upk(na, nb, n2);
    const u64 rinv2 = pk(frcp(na), frcp(nb));
    const u64 r2 = add2(rinv2, rinv2);
    return mkq2(fma2(omr, r2, NONE2), mul2(wy, r2), mul2(wz, r2), mul2(ww, r2));
}

// Transpose two float4 quats (s0, s1) into packed form with negs.
__device__ __forceinline__ Q2 pack_pair(const float4 a, const float4 b) {
    return mkq2(pk(a.x, b.x), pk(a.y, b.y), pk(a.z, b.z), pk(a.w, b.w));
}

// Scalar float4 quaternion helpers (K2 only)
__device__ __forceinline__ float4 qmuladd(const float4 a, const float4 b, const float4 c) {
    float4 r;
    r.x = fmaf(a.x, b.x, fmaf(-a.y, b.y, fmaf(-a.z, b.z, fmaf(-a.w, b.w, c.x))));
    r.y = fmaf(a.x, b.y, fmaf( a.y, b.x, fmaf( a.z, b.w, fmaf(-a.w, b.z, c.y))));
    r.z = fmaf(a.x, b.z, fmaf(-a.y, b.w, fmaf( a.z, b.x, fmaf( a.w, b.y, c.z))));
    r.w = fmaf(a.x, b.w, fmaf( a.y, b.z, fmaf(-a.z, b.y, fmaf( a.w, b.x, c.w))));
    return r;
}
__device__ __forceinline__ float4 qmul(const float4 a, const float4 b) {
    return qmuladd(a, b, make_float4(0.f, 0.f, 0.f, 0.f));
}
__device__ __forceinline__ float4 shfl_up4(const float4 v, int off) {
    float4 r;
    r.x = __shfl_up_sync(0xffffffffu, v.x, off);
    r.y = __shfl_up_sync(0xffffffffu, v.y, off);
    r.z = __shfl_up_sync(0xffffffffu, v.z, off);
    r.w = __shfl_up_sync(0xffffffffu, v.w, off);
    return r;
}

// SH=2 thread decomposition: lane bits [0:4)=d_low4, bit4=s-half, d_hi, c, b.
struct DeH { int b, c, d, s0, hbit; };
__device__ __forceinline__ DeH decompH(int gt) {
    DeH r;
    const int lane16 = gt & 15;
    r.hbit = (gt >> 4) & 1;
    const int rest = gt >> 5;
    r.d = ((rest & 31) << 4) + lane16;
    r.c = (rest >> 5) & (NC - 1);
    r.b = rest >> 12;
    r.s0 = r.hbit * SH;
    return r;
}

// Load packed ah (0.5*A quaternion) for the thread's s-pair.
__device__ __forceinline__ P4 load_ah2(const float* __restrict__ A_log,
                                       const float* __restrict__ A_i,
                                       const float* __restrict__ A_j,
                                       const float* __restrict__ A_k,
                                       int d, int s0) {
    const int a0 = d * SQ + s0, a1 = a0 + 1;
    P4 r;
    r.x = pk(-0.5f * __expf(A_log[a0]), -0.5f * __expf(A_log[a1]));
    r.y = pk(0.5f * A_i[a0], 0.5f * A_i[a1]);
    r.z = pk(0.5f * A_j[a0], 0.5f * A_j[a1]);
    r.w = pk(0.5f * A_k[a0], 0.5f * A_k[a1]);
    return r;
}

// ---------------------------------------------------------------------------
// K1: per-(b, chunk, d, s-half) thread — chunk transforms (Q, H), s-pair SIMD.
// ---------------------------------------------------------------------------
__global__ void __launch_bounds__(256, 3)
k_summary(const float* __restrict__ u, const float* __restrict__ dt,
          const float* __restrict__ Bin,
          const float* __restrict__ A_log, const float* __restrict__ A_i,
          const float* __restrict__ A_j,  const float* __restrict__ A_k)
{
    const DeH de = decompH(blockIdx.x * blockDim.x + threadIdx.x);
    const int d = de.d, c = de.c, b = de.b, s0 = de.s0;

    const P4 ah2 = load_ah2(A_log, A_i, A_j, A_k, d, s0);
    const u64 nahx2 = neg2(ah2.x);

    const float4* __restrict__ u4 = (const float4*)u;
    const float4* __restrict__ B4 = (const float4*)Bin;

    const int t0 = c * CHUNKF;
    P4 Qp, Hp;
    const P4 zero4 = { 0ull, 0ull, 0ull, 0ull };

#pragma unroll 1
    for (int i = 0; i < CHUNKF; i++) {
        const int td = b * LEN + t0 + i;
        const float  dtv = dt[td * DQ + d];
        const float4 uu  = u4[td * DQ + d];
        const float  hdt = 0.5f * dtv;
        const u64 dt2 = pk(dtv, dtv);
        // us splats (same value on both halves; u is s-independent)
        P4 us2;
        { const float a = uu.x * hdt; us2.x = pk(a, a); }
        { const float a = uu.y * hdt; us2.y = pk(a, a); }
        { const float a = uu.z * hdt; us2.z = pk(a, a); }
        { const float a = uu.w * hdt; us2.w = pk(a, a); }

        const Q2 Bq2 = pack_pair(B4[td * SQ + s0], B4[td * SQ + s0 + 1]);
        const P4 Bu0 = qmad2(Bq2, us2, zero4);

        const Q2 q2 = step_q2(dt2, ah2, nahx2);

        if (i == 0) {
            Hp = qmad2(q2, Bu0, Bu0);               // H = q(x)Bu0 + Bu0
            Qp.x = q2.x; Qp.y = q2.y; Qp.z = q2.z; Qp.w = q2.w;
        } else {
            P4 X; X.x = add2(Hp.x, Bu0.x); X.y = add2(Hp.y, Bu0.y);
                  X.z = add2(Hp.z, Bu0.z); X.w = add2(Hp.w, Bu0.w);
            Hp = qmad2(q2, X, Bu0);                 // H = q(x)(H+Bu0) + Bu0
            Qp = qmad2(q2, Qp, zero4);              // Q = q(x)Q
        }
    }

    // Unpack s-pair -> two float4 quats each, store for K2.
    {
        float x0,x1,y0,y1,z0,z1,w0,w1;
        const int i0 = ((b * NC + c) * SQ + s0) * DQ + d;
        const int i1 = i0 + DQ;
        upk(x0,x1,Qp.x); upk(y0,y1,Qp.y); upk(z0,z1,Qp.z); upk(w0,w1,Qp.w);
        g_Q[i0] = make_float4(x0,y0,z0,w0);
        g_Q[i1] = make_float4(x1,y1,z1,w1);
        upk(x0,x1,Hp.x); upk(y0,y1,Hp.y); upk(z0,z1,Hp.z); upk(w0,w1,Hp.w);
        g_H[i0] = make_float4(x0,y0,z0,w0);
        g_H[i1] = make_float4(x1,y1,z1,w1);
    }
}

// ---------------------------------------------------------------------------
// K2: warp-parallel affine scan (scalar float4; unchanged from R8).
// ---------------------------------------------------------------------------
__global__ void __launch_bounds__(256)
k_carry()
{
    const int gt = blockIdx.x * blockDim.x + threadIdx.x;
    const int lane = gt & 31;
    const int w = gt >> 5;                 // chain id in [0, BSZ*SQ*DQ)
    const int d = w & (DQ - 1);
    const int s = (w >> 9) & (SQ - 1);
    const int b = w >> 11;

    const int cstride = SQ * DQ;
    const int base = (b * NC * SQ + s) * DQ + d;
    const int c0 = lane * NCL;

    float4 Qc[NCL], Hc[NCL];
#pragma unroll
    for (int j = 0; j < NCL; j++) {
        const int idx = base + (c0 + j) * cstride;
        Qc[j] = g_Q[idx];
        Hc[j] = g_H[idx];
    }

    float4 Qs = Qc[0], Hs = Hc[0];
#pragma unroll
    for (int j = 1; j < NCL; j++) {
        Hs = qmuladd(Qc[j], Hs, Hc[j]);
        Qs = qmul(Qc[j], Qs);
    }

#pragma unroll
    for (int off = 1; off < 32; off <<= 1) {
        const float4 Qp = shfl_up4(Qs, off);
        const float4 Hp = shfl_up4(Hs, off);
        if (lane >= off) {
            Hs = qmuladd(Qs, Hp, Hs);
            Qs = qmul(Qs, Qp);
        }
    }

    float4 h = shfl_up4(Hs, 1);
    if (lane == 0) h = make_float4(0.f, 0.f, 0.f, 0.f);

#pragma unroll
    for (int j = 0; j < NCL; j++) {
        const int idx = base + (c0 + j) * cstride;
        g_Hin[idx] = h;
        h = qmuladd(Qc[j], h, Hc[j]);
    }
}

// ---------------------------------------------------------------------------
// K3: per-(b, chunk, d, s-half) thread — recompute with carry, s-pair SIMD.
//     y reduce: packed add within thread across pairs via shfl_xor(16) on u64,
//     then lo+hi per component; hbit==0 lanes store float4.
// ---------------------------------------------------------------------------
__global__ void __launch_bounds__(256, 3)
k_final(const float* __restrict__ u, const float* __restrict__ dt,
        const float* __restrict__ Bin, const float* __restrict__ Cin,
        const float* __restrict__ A_log, const float* __restrict__ A_i,
        const float* __restrict__ A_j,  const float* __restrict__ A_k,
        float* __restrict__ out)
{
    const DeH de = decompH(blockIdx.x * blockDim.x + threadIdx.x);
    const int d = de.d, c = de.c, b = de.b, s0 = de.s0;

    const P4 ah2 = load_ah2(A_log, A_i, A_j, A_k, d, s0);
    const u64 nahx2 = neg2(ah2.x);

    P4 hq;
    {
        const int i0 = ((b * NC + c) * SQ + s0) * DQ + d;
        const float4 h0 = g_Hin[i0];
        const float4 h1 = g_Hin[i0 + DQ];
        hq.x = pk(h0.x, h1.x); hq.y = pk(h0.y, h1.y);
        hq.z = pk(h0.z, h1.z); hq.w = pk(h0.w, h1.w);
    }

    const float4* __restrict__ u4 = (const float4*)u;
    const float4* __restrict__ B4 = (const float4*)Bin;
    const float4* __restrict__ C4 = (const float4*)Cin;
    float4* __restrict__ o4 = (float4*)out;

    const int t0 = c * CHUNKF;
    const P4 zero4 = { 0ull, 0ull, 0ull, 0ull };

#pragma unroll 1
    for (int i = 0; i < CHUNKF; i++) {
        const int td = b * LEN + t0 + i;
        const float  dtv = dt[td * DQ + d];
        const float4 uu  = u4[td * DQ + d];
        const float  hdt = 0.5f * dtv;
        const u64 dt2 = pk(dtv, dtv);
        P4 us2;
        { const float a = uu.x * hdt; us2.x = pk(a, a); }
        { const float a = uu.y * hdt; us2.y = pk(a, a); }
        { const float a = uu.z * hdt; us2.z = pk(a, a); }
        { const float a = uu.w * hdt; us2.w = pk(a, a); }

        const Q2 Bq2 = pack_pair(B4[td * SQ + s0], B4[td * SQ + s0 + 1]);
        const P4 Bu0 = qmad2(Bq2, us2, zero4);

        const Q2 q2 = step_q2(dt2, ah2, nahx2);

        // h = q (x) (h + Bu0) + Bu0
        P4 X; X.x = add2(hq.x, Bu0.x); X.y = add2(hq.y, Bu0.y);
              X.z = add2(hq.z, Bu0.z); X.w = add2(hq.w, Bu0.w);
        hq = qmad2(q2, X, Bu0);

        // y = C (x) h  (packed over this thread's s-pair)
        const Q2 Cq2 = pack_pair(C4[td * SQ + s0], C4[td * SQ + s0 + 1]);
        P4 y = qmad2(Cq2, hq, zero4);

        // Combine with the other s-half thread (lane bit 4), packed adds.
        y.x = add2(y.x, __shfl_xor_sync(0xffffffffu, y.x, 16));
        y.y = add2(y.y, __shfl_xor_sync(0xffffffffu, y.y, 16));
        y.z = add2(y.z, __shfl_xor_sync(0xffffffffu, y.z, 16));
        y.w = add2(y.w, __shfl_xor_sync(0xffffffffu, y.w, 16));

        if (de.hbit == 0) {
            float a0, a1, b0v, b1v, c0v, c1v, d0v, d1v;
            upk(a0, a1, y.x); upk(b0v, b1v, y.y);
            upk(c0v, c1v, y.z); upk(d0v, d1v, y.w);
            o4[td * DQ + d] = make_float4(a0 + a1, b0v + b1v, c0v + c1v, d0v + d1v);
        }
    }
}

// ---------------------------------------------------------------------------
// Launch (single stream, R8 structure)
// ---------------------------------------------------------------------------
extern "C" void kernel_launch(void* const* d_in, const int* in_sizes, int n_in,
                              void* d_out, int out_size)
{
    const float* u     = (const float*)d_in[0];
    const float* dt    = (const float*)d_in[1];
    const float* Bin   = (const float*)d_in[2];
    const float* Cin   = (const float*)d_in[3];
    const float* A_log = (const float*)d_in[4];
    const float* A_i   = (const float*)d_in[5];
    const float* A_j   = (const float*)d_in[6];
    const float* A_k   = (const float*)d_in[7];
    float* out = (float*)d_out;

    const int k13_threads = BSZ * NC * DQ * 2;      // 262144
    const int k2_threads  = BSZ * SQ * DQ * 32;     // 131072 (warp per chain)

    k_summary<<<k13_threads / 256, 256>>>(u, dt, Bin, A_log, A_i, A_j, A_k);
    k_carry<<<k2_threads / 256, 256>>>();
    k_final<<<k13_threads / 256, 256>>>(u, dt, Bin, Cin, A_log, A_i, A_j, A_k, out);
}

// round 13
// speedup vs baseline: 1.2440x; 1.2440x over previous
#include <cuda_runtime.h>

// Problem constants (fixed by the reference)
#define BSZ    2
#define LEN    2048
#define DQ     512
#define SQ     4
#define SH     2                 // s-lanes per thread (K1 and K3)
#define NC     128               // fine chunks along L (all kernels)
#define CHUNKF (LEN / NC)        // 16 steps per fine chunk
#define NCL    (NC / 32)         // fine chunks per lane in K2 warp scan (4)
#define EPSQ   1e-6f

// Scratch: chunk summaries and carries, laid out [b][chunk][s][d].
__device__ float4 g_Q  [BSZ * NC * SQ * DQ];
__device__ float4 g_H  [BSZ * NC * SQ * DQ];
__device__ float4 g_Hin[BSZ * NC * SQ * DQ];

// ---------------------------------------------------------------------------
// Quaternion helpers
// ---------------------------------------------------------------------------
__device__ __forceinline__ float4 qmuladd(const float4 a, const float4 b, const float4 c) {
    float4 r;
    r.x = fmaf(a.x, b.x, fmaf(-a.y, b.y, fmaf(-a.z, b.z, fmaf(-a.w, b.w, c.x))));
    r.y = fmaf(a.x, b.y, fmaf( a.y, b.x, fmaf( a.z, b.w, fmaf(-a.w, b.z, c.y))));
    r.z = fmaf(a.x, b.z, fmaf(-a.y, b.w, fmaf( a.z, b.x, fmaf( a.w, b.y, c.z))));
    r.w = fmaf(a.x, b.w, fmaf( a.y, b.z, fmaf(-a.z, b.y, fmaf( a.w, b.x, c.w))));
    return r;
}
__device__ __forceinline__ float4 qmul(const float4 a, const float4 b) {
    return qmuladd(a, b, make_float4(0.f, 0.f, 0.f, 0.f));
}
__device__ __forceinline__ float4 add4(const float4 a, const float4 b) {
    return make_float4(a.x + b.x, a.y + b.y, a.z + b.z, a.w + b.w);
}

// Approximate reciprocal (no Newton step): rel err ~2.4e-7, fine vs 1e-3 tol.
__device__ __forceinline__ float frcp(float x) {
    float r; asm("rcp.approx.f32 %0, %1;" : "=f"(r) : "f"(x)); return r;
}

// Per-(d,s) transition invariants: pax = +0.5*exp(A_log) (= -a_x),
// av = 0.5*(A_i,A_j,A_k), S = |av|^2.
struct AInv { float pax, ay, az, aw, S; };

// Optimized per-step transition quaternion (9.5 FMA-pipe ops amortized):
//   omr = 1 + dt*pax ; vve = dt^2*S + eps ; n2 = omr^2 + vve ; r2 = 2/n2
//   q = (omr*r2 - 1, (dt*r2)*av)
__device__ __forceinline__ float4 step_q(const float dtv, const float dt2,
                                         const AInv& a) {
    const float omr = fmaf(dtv, a.pax, 1.0f);
    const float vve = fmaf(dt2, a.S, EPSQ);
    const float n2  = fmaf(omr, omr, vve);
    const float r2  = frcp(n2) * 2.0f;
    const float e   = dtv * r2;
    return make_float4(fmaf(omr, r2, -1.0f), e * a.ay, e * a.az, e * a.aw);
}

__device__ __forceinline__ AInv load_ainv(const float* __restrict__ A_log,
                                          const float* __restrict__ A_i,
                                          const float* __restrict__ A_j,
                                          const float* __restrict__ A_k,
                                          int ai) {
    AInv r;
    r.pax = 0.5f * __expf(A_log[ai]);
    r.ay  = 0.5f * A_i[ai];
    r.az  = 0.5f * A_j[ai];
    r.aw  = 0.5f * A_k[ai];
    r.S   = fmaf(r.ay, r.ay, fmaf(r.az, r.az, r.aw * r.aw));
    return r;
}

__device__ __forceinline__ float4 shfl_up4(const float4 v, int off) {
    float4 r;
    r.x = __shfl_up_sync(0xffffffffu, v.x, off);
    r.y = __shfl_up_sync(0xffffffffu, v.y, off);
    r.z = __shfl_up_sync(0xffffffffu, v.z, off);
    r.w = __shfl_up_sync(0xffffffffu, v.w, off);
    return r;
}

// SH=2 thread decomposition: lane bits [0:4)=d_low4, bit4=s-half, d_hi, c, b.
struct DeH { int b, c, d, s0, hbit; };
__device__ __forceinline__ DeH decompH(int gt) {
    DeH r;
    const int lane16 = gt & 15;
    r.hbit = (gt >> 4) & 1;
    const int rest = gt >> 5;
    r.d = ((rest & 31) << 4) + lane16;
    r.c = (rest >> 5) & (NC - 1);
    r.b = rest >> 12;
    r.s0 = r.hbit * SH;
    return r;
}

// ---------------------------------------------------------------------------
// K1: per-(b, chunk, d, s-half) thread — chunk transforms (Q, H).
// ---------------------------------------------------------------------------
__global__ void __launch_bounds__(256, 4)
k_summary(const float* __restrict__ u, const float* __restrict__ dt,
          const float* __restrict__ Bin,
          const float* __restrict__ A_log, const float* __restrict__ A_i,
          const float* __restrict__ A_j,  const float* __restrict__ A_k)
{
    const DeH de = decompH(blockIdx.x * blockDim.x + threadIdx.x);
    const int d = de.d, c = de.c, b = de.b, s0 = de.s0;

    AInv av[SH];
#pragma unroll
    for (int s = 0; s < SH; s++)
        av[s] = load_ainv(A_log, A_i, A_j, A_k, d * SQ + s0 + s);

    const float4* __restrict__ u4 = (const float4*)u;
    const float4* __restrict__ B4 = (const float4*)Bin;

    const int t0 = c * CHUNKF;
    float4 Q[SH], H[SH];

    {   // peel first step: Q = q, H = q(x)Bu0 + Bu0
        const int td = b * LEN + t0;
        const float  dtv = dt[td * DQ + d];
        const float4 uu  = u4[td * DQ + d];
        const float  hdt = 0.5f * dtv;
        const float  dt2 = dtv * dtv;
        const float4 us  = make_float4(uu.x * hdt, uu.y * hdt, uu.z * hdt, uu.w * hdt);
#pragma unroll
        for (int s = 0; s < SH; s++) {
            const float4 Bq = B4[td * SQ + s0 + s];
            const float4 q  = step_q(dtv, dt2, av[s]);
            const float4 Bu0 = qmul(Bq, us);
            Q[s] = q;
            H[s] = qmuladd(q, Bu0, Bu0);
        }
    }

#pragma unroll 2
    for (int i = 1; i < CHUNKF; i++) {
        const int td = b * LEN + t0 + i;
        const float  dtv = dt[td * DQ + d];
        const float4 uu  = u4[td * DQ + d];
        const float  hdt = 0.5f * dtv;
        const float  dt2 = dtv * dtv;
        const float4 us  = make_float4(uu.x * hdt, uu.y * hdt, uu.z * hdt, uu.w * hdt);
#pragma unroll
        for (int s = 0; s < SH; s++) {
            const float4 Bq = B4[td * SQ + s0 + s];
            const float4 q  = step_q(dtv, dt2, av[s]);
            const float4 Bu0 = qmul(Bq, us);
            H[s] = qmuladd(q, add4(H[s], Bu0), Bu0);
            Q[s] = qmul(q, Q[s]);
        }
    }

#pragma unroll
    for (int s = 0; s < SH; s++) {
        const int idx = ((b * NC + c) * SQ + s0 + s) * DQ + d;
        g_Q[idx] = Q[s];
        g_H[idx] = H[s];
    }
}

// ---------------------------------------------------------------------------
// K2: warp-parallel affine scan. One warp per (b,s,d) chain; each lane owns
//     NCL=4 consecutive fine chunks. Local compose -> shfl_up scan -> replay.
// ---------------------------------------------------------------------------
__global__ void __launch_bounds__(256)
k_carry()
{
    const int gt = blockIdx.x * blockDim.x + threadIdx.x;
    const int lane = gt & 31;
    const int w = gt >> 5;                 // chain id in [0, BSZ*SQ*DQ)
    const int d = w & (DQ - 1);
    const int s = (w >> 9) & (SQ - 1);
    const int b = w >> 11;

    const int cstride = SQ * DQ;
    const int base = (b * NC * SQ + s) * DQ + d;
    const int c0 = lane * NCL;

    float4 Qc[NCL], Hc[NCL];
#pragma unroll
    for (int j = 0; j < NCL; j++) {
        const int idx = base + (c0 + j) * cstride;
        Qc[j] = g_Q[idx];
        Hc[j] = g_H[idx];
    }

    // Local inclusive composition over this lane's 4 chunks.
    float4 Qs = Qc[0], Hs = Hc[0];
#pragma unroll
    for (int j = 1; j < NCL; j++) {
        Hs = qmuladd(Qc[j], Hs, Hc[j]);
        Qs = qmul(Qc[j], Qs);
    }

    // Warp inclusive scan of the affine pair.
#pragma unroll
    for (int off = 1; off < 32; off <<= 1) {
        const float4 Qp = shfl_up4(Qs, off);
        const float4 Hp = shfl_up4(Hs, off);
        if (lane >= off) {
            Hs = qmuladd(Qs, Hp, Hs);   // pre-update Qs = current segment
            Qs = qmul(Qs, Qp);
        }
    }

    // Exclusive prefix = inclusive of lane-1 (identity at lane 0).
    float4 h = shfl_up4(Hs, 1);
    if (lane == 0) h = make_float4(0.f, 0.f, 0.f, 0.f);

    // Replay: emit carry-in for each owned chunk.
#pragma unroll
    for (int j = 0; j < NCL; j++) {
        const int idx = base + (c0 + j) * cstride;
        g_Hin[idx] = h;
        h = qmuladd(Qc[j], h, Hc[j]);
    }
}

// ---------------------------------------------------------------------------
// K3: per-(b, chunk, d, s-half) thread — recompute with carry, emit y.
//     Pair-sum over s-halves via shfl_xor(16); hbit==0 lanes store float4.
// ---------------------------------------------------------------------------
__global__ void __launch_bounds__(256, 4)
k_final(const float* __restrict__ u, const float* __restrict__ dt,
        const float* __restrict__ Bin, const float* __restrict__ Cin,
        const float* __restrict__ A_log, const float* __restrict__ A_i,
        const float* __restrict__ A_j,  const float* __restrict__ A_k,
        float* __restrict__ out)
{
    const DeH de = decompH(blockIdx.x * blockDim.x + threadIdx.x);
    const int d = de.d, c = de.c, b = de.b, s0 = de.s0;

    AInv av[SH];
#pragma unroll
    for (int s = 0; s < SH; s++)
        av[s] = load_ainv(A_log, A_i, A_j, A_k, d * SQ + s0 + s);

    float4 h[SH];
#pragma unroll
    for (int s = 0; s < SH; s++)
        h[s] = g_Hin[((b * NC + c) * SQ + s0 + s) * DQ + d];

    const float4* __restrict__ u4 = (const float4*)u;
    const float4* __restrict__ B4 = (const float4*)Bin;
    const float4* __restrict__ C4 = (const float4*)Cin;
    float4* __restrict__ o4 = (float4*)out;

    const int t0 = c * CHUNKF;
#pragma unroll 2
    for (int i = 0; i < CHUNKF; i++) {
        const int td = b * LEN + t0 + i;
        const float  dtv = dt[td * DQ + d];
        const float4 uu  = u4[td * DQ + d];
        const float  hdt = 0.5f * dtv;
        const float  dt2 = dtv * dtv;
        const float4 us  = make_float4(uu.x * hdt, uu.y * hdt, uu.z * hdt, uu.w * hdt);
        float4 y = make_float4(0.f, 0.f, 0.f, 0.f);
#pragma unroll
        for (int s = 0; s < SH; s++) {
            const float4 Bq = B4[td * SQ + s0 + s];
            const float4 Cq = C4[td * SQ + s0 + s];
            const float4 q  = step_q(dtv, dt2, av[s]);
            const float4 Bu0 = qmul(Bq, us);
            h[s] = qmuladd(q, add4(h[s], Bu0), Bu0);
            y = qmuladd(Cq, h[s], y);
        }
        // Pair-reduce across s-halves (lane bit 4).
        y.x += __shfl_xor_sync(0xffffffffu, y.x, 16);
        y.y += __shfl_xor_sync(0xffffffffu, y.y, 16);
        y.z += __shfl_xor_sync(0xffffffffu, y.z, 16);
        y.w += __shfl_xor_sync(0xffffffffu, y.w, 16);
        if (de.hbit == 0)
            o4[td * DQ + d] = y;
    }
}

// ---------------------------------------------------------------------------
// Launch (single stream, R8 structure)
// ---------------------------------------------------------------------------
extern "C" void kernel_launch(void* const* d_in, const int* in_sizes, int n_in,
                              void* d_out, int out_size)
{
    const float* u     = (const float*)d_in[0];
    const float* dt    = (const float*)d_in[1];
    const float* Bin   = (const float*)d_in[2];
    const float* Cin   = (const float*)d_in[3];
    const float* A_log = (const float*)d_in[4];
    const float* A_i   = (const float*)d_in[5];
    const float* A_j   = (const float*)d_in[6];
    const float* A_k   = (const float*)d_in[7];
    float* out = (float*)d_out;

    const int k13_threads = BSZ * NC * DQ * 2;      // 262144
    const int k2_threads  = BSZ * SQ * DQ * 32;     // 131072 (warp per chain)

    k_summary<<<k13_threads / 256, 256>>>(u, dt, Bin, A_log, A_i, A_j, A_k);
    k_carry<<<k2_threads / 256, 256>>>();
    k_final<<<k13_threads / 256, 256>>>(u, dt, Bin, Cin, A_log, A_i, A_j, A_k, out);
}